// round 1
// baseline (speedup 1.0000x reference)
#include <cuda_runtime.h>

// ---------------------------------------------------------------------------
// Problem constants
// ---------------------------------------------------------------------------
#define TT     16
#define NN     20000
#define EE     320000
#define PP     4096
#define DIN    128
#define HH     256
#define NHEAD  8
#define NLAY   2
#define FF     2048
#define DM     512
#define HD     64
#define NTOK   (TT * PP)     // 65536

// ---------------------------------------------------------------------------
// Scratch blobs (no allocations allowed)
// ---------------------------------------------------------------------------
constexpr size_t F_BUFA = 0;                             // [20000, 256]  sage L1 input [x|agg]
constexpr size_t F_H1   = F_BUFA + 20000ull * 256;       // [20000, 256]  sage L1 out
constexpr size_t F_BUFB = F_H1   + 20000ull * 256;       // [20000, 512]  sage L2 input [h1|agg]
constexpr size_t F_H2   = F_BUFB + 20000ull * 512;       // [20000, 256]  sage L2 out
constexpr size_t F_WC1  = F_H2   + 20000ull * 256;       // [256, 256]    stacked W1
constexpr size_t F_WC2  = F_WC1  + 256ull * 256;         // [512, 256]    stacked W2
constexpr size_t F_WQKV = F_WC2  + 512ull * 256;         // [2, 512, 1536]
constexpr size_t F_BQKV = F_WQKV + 2ull * 512 * 1536;    // [2, 1536]
constexpr size_t F_H    = F_BQKV + 2ull * 1536;          // [65536, 512]  transformer hidden
constexpr size_t F_QKV  = F_H    + (size_t)NTOK * 512;   // [65536, 1536]
constexpr size_t F_TMP  = F_QKV  + (size_t)NTOK * 1536;  // [65536, 512]
constexpr size_t F_FF   = F_TMP  + (size_t)NTOK * 512;   // [65536, 2048]
constexpr size_t F_TOTAL= F_FF   + (size_t)NTOK * 2048;

__device__ float g_fblob[F_TOTAL];

constexpr size_t I_DEG = 0;
constexpr size_t I_CUR = 20000;
constexpr size_t I_OFF = 40000;          // N+1
constexpr size_t I_CSR = 60001;
constexpr size_t I_TOTAL = I_CSR + (size_t)EE;
__device__ int g_iblob[I_TOTAL];

// ---------------------------------------------------------------------------
// CSR construction
// ---------------------------------------------------------------------------
__global__ void zero_int_kernel(int* __restrict__ p, int n) {
    int i = blockIdx.x * blockDim.x + threadIdx.x;
    if (i < n) p[i] = 0;
}

__global__ void hist_kernel(const int* __restrict__ dst, int* __restrict__ deg) {
    int e = blockIdx.x * blockDim.x + threadIdx.x;
    if (e < EE) atomicAdd(&deg[dst[e]], 1);
}

__global__ void scan_kernel(const int* __restrict__ deg, int* __restrict__ off) {
    __shared__ int sd[1024];
    __shared__ int carry;
    int tid = threadIdx.x;
    if (tid == 0) { carry = 0; off[0] = 0; }
    __syncthreads();
    for (int base = 0; base < NN; base += 1024) {
        int i = base + tid;
        int v = (i < NN) ? deg[i] : 0;
        sd[tid] = v;
        __syncthreads();
        for (int o = 1; o < 1024; o <<= 1) {
            int t = (tid >= o) ? sd[tid - o] : 0;
            __syncthreads();
            sd[tid] += t;
            __syncthreads();
        }
        if (i < NN) off[i + 1] = carry + sd[tid];
        __syncthreads();
        if (tid == 0) carry += sd[1023];
        __syncthreads();
    }
}

__global__ void fill_kernel(const int* __restrict__ src, const int* __restrict__ dst,
                            const int* __restrict__ off, int* __restrict__ cur,
                            int* __restrict__ csrc) {
    int e = blockIdx.x * blockDim.x + threadIdx.x;
    if (e < EE) {
        int d = dst[e];
        int p = atomicAdd(&cur[d], 1);
        csrc[off[d] + p] = src[e];
    }
}

// ---------------------------------------------------------------------------
// Build A = [self | mean_agg] for a SAGE layer.  blockDim = F, grid = NN.
// ---------------------------------------------------------------------------
__global__ void build_A_kernel(const float* __restrict__ feat, int F,
                               const int* __restrict__ off, const int* __restrict__ csrc,
                               float* __restrict__ out) {
    int n = blockIdx.x;
    int f = threadIdx.x;
    float self = feat[(size_t)n * F + f];
    int s = off[n], e = off[n + 1];
    float acc = 0.f;
    int i = s;
    for (; i + 4 <= e; i += 4) {
        int a0 = csrc[i], a1 = csrc[i + 1], a2 = csrc[i + 2], a3 = csrc[i + 3];
        float v0 = feat[(size_t)a0 * F + f];
        float v1 = feat[(size_t)a1 * F + f];
        float v2 = feat[(size_t)a2 * F + f];
        float v3 = feat[(size_t)a3 * F + f];
        acc += v0 + v1 + v2 + v3;
    }
    for (; i < e; i++) acc += feat[(size_t)csrc[i] * F + f];
    int d = e - s; if (d < 1) d = 1;
    size_t ob = (size_t)n * (2 * F);
    out[ob + f]     = self;
    out[ob + F + f] = acc / (float)d;
}

// ---------------------------------------------------------------------------
// SGEMM: C[M,N] = A[M,K] @ B[K,N] (+bias) (+relu).  Row-major everywhere.
// 128x128 tile, BK=8, 256 threads, 8x8 per thread.
// Requires: K % 8 == 0, N % 128 == 0 (true for all call sites). M guarded.
// ---------------------------------------------------------------------------
template <int RELU, int BIAS>
__global__ void __launch_bounds__(256)
sgemm_kernel(const float* __restrict__ A, const float* __restrict__ B,
             const float* __restrict__ bias, float* __restrict__ C,
             int M, int K, int N) {
    __shared__ float As[8][128];
    __shared__ float Bs[8][128];
    int tid = threadIdx.x;
    int bm = blockIdx.y * 128;
    int bn = blockIdx.x * 128;
    int tx = tid & 15, ty = tid >> 4;
    int row0 = ty * 8, col0 = tx * 8;
    float acc[8][8];
#pragma unroll
    for (int i = 0; i < 8; i++)
#pragma unroll
        for (int j = 0; j < 8; j++) acc[i][j] = 0.f;

    int arow = tid >> 1;
    int acol = (tid & 1) * 4;
    int brow = tid >> 5;
    int bcol = (tid & 31) * 4;
    const float* Aptr = A + (size_t)(bm + arow) * K + acol;
    const float* Bptr = B + (size_t)brow * N + bn + bcol;
    bool arow_ok = (bm + arow) < M;

    for (int k0 = 0; k0 < K; k0 += 8) {
        float4 av = arow_ok ? *(const float4*)Aptr : make_float4(0.f, 0.f, 0.f, 0.f);
        float4 bv = *(const float4*)Bptr;
        As[acol + 0][arow] = av.x;
        As[acol + 1][arow] = av.y;
        As[acol + 2][arow] = av.z;
        As[acol + 3][arow] = av.w;
        *(float4*)&Bs[brow][bcol] = bv;
        __syncthreads();
#pragma unroll
        for (int kk = 0; kk < 8; kk++) {
            float a[8], b[8];
            *(float4*)&a[0] = *(const float4*)&As[kk][row0];
            *(float4*)&a[4] = *(const float4*)&As[kk][row0 + 4];
            *(float4*)&b[0] = *(const float4*)&Bs[kk][col0];
            *(float4*)&b[4] = *(const float4*)&Bs[kk][col0 + 4];
#pragma unroll
            for (int i = 0; i < 8; i++)
#pragma unroll
                for (int j = 0; j < 8; j++) acc[i][j] += a[i] * b[j];
        }
        __syncthreads();
        Aptr += 8;
        Bptr += (size_t)8 * N;
    }

#pragma unroll
    for (int i = 0; i < 8; i++) {
        int r = bm + row0 + i;
        if (r >= M) break;
        float* Crow = C + (size_t)r * N + bn + col0;
#pragma unroll
        for (int j = 0; j < 8; j++) {
            float v = acc[i][j];
            if (BIAS) v += bias[bn + col0 + j];
            if (RELU) v = fmaxf(v, 0.f);
            Crow[j] = v;
        }
    }
}

// ---------------------------------------------------------------------------
// Row L2-normalize, [NN, 256] in place.  grid = NN, block = 256.
// ---------------------------------------------------------------------------
__global__ void rownorm_kernel(float* __restrict__ h) {
    int n = blockIdx.x;
    int f = threadIdx.x;
    float v = h[(size_t)n * 256 + f];
    float s = v * v;
    __shared__ float red[8];
    for (int o = 16; o; o >>= 1) s += __shfl_xor_sync(0xffffffffu, s, o);
    if ((f & 31) == 0) red[f >> 5] = s;
    __syncthreads();
    float tot = red[0] + red[1] + red[2] + red[3] + red[4] + red[5] + red[6] + red[7];
    float norm = fmaxf(sqrtf(tot), 1e-12f);
    h[(size_t)n * 256 + f] = v / norm;
}

// Gather selected rows into att_in output AND transformer hidden init.
__global__ void gather_kernel(const float* __restrict__ h2, const int* __restrict__ idx,
                              float* __restrict__ att_out, float* __restrict__ hinit,
                              int t, int g) {
    int p = blockIdx.x;
    int f = threadIdx.x;      // 256
    int n = idx[p];
    float v = h2[(size_t)n * 256 + f];
    size_t o = ((size_t)(t * PP + p)) * DM + g * 256 + f;
    att_out[o] = v;
    hinit[o]   = v;
}

// ---------------------------------------------------------------------------
// Banded attention: window 4, T=16.  One block per (p, head), 128 threads.
// ---------------------------------------------------------------------------
__global__ void attn_kernel(const float* __restrict__ qkv, float* __restrict__ out) {
    int ph = blockIdx.x;
    int p = ph >> 3;
    int h = ph & 7;
    __shared__ float qs[16][64], ks[16][64], vs[16][64];
    int tid = threadIdx.x;
    for (int i = tid; i < 1024; i += 128) {
        int t = i >> 6, d = i & 63;
        const float* b = qkv + ((size_t)(t * PP + p)) * 1536 + h * 64 + d;
        qs[t][d] = b[0];
        ks[t][d] = b[512];
        vs[t][d] = b[1024];
    }
    __syncthreads();
    int warp = tid >> 5, lane = tid & 31;
    for (int t = warp; t < 16; t += 4) {
        int s0 = t - 3; if (s0 < 0) s0 = 0;
        int ns = t - s0 + 1;
        float sc[4];
        float mx = -1e30f;
        for (int si = 0; si < ns; si++) {
            int s = s0 + si;
            float d0 = qs[t][lane] * ks[s][lane] + qs[t][lane + 32] * ks[s][lane + 32];
            for (int o = 16; o; o >>= 1) d0 += __shfl_xor_sync(0xffffffffu, d0, o);
            d0 *= 0.125f;   // 1/sqrt(64)
            sc[si] = d0;
            mx = fmaxf(mx, d0);
        }
        float sum = 0.f;
        for (int si = 0; si < ns; si++) { sc[si] = expf(sc[si] - mx); sum += sc[si]; }
        float inv = 1.f / sum;
        float o0 = 0.f, o1 = 0.f;
        for (int si = 0; si < ns; si++) {
            int s = s0 + si;
            o0 += sc[si] * vs[s][lane];
            o1 += sc[si] * vs[s][lane + 32];
        }
        size_t ob = ((size_t)(t * PP + p)) * DM + h * 64;
        out[ob + lane]      = o0 * inv;
        out[ob + lane + 32] = o1 * inv;
    }
}

// ---------------------------------------------------------------------------
// h = LayerNorm(h + delta) * g + b.  grid = NTOK, block = 128, row = 512.
// ---------------------------------------------------------------------------
__global__ void resid_ln_kernel(float* __restrict__ h, const float* __restrict__ delta,
                                const float* __restrict__ g, const float* __restrict__ b) {
    int row = blockIdx.x;
    int tid = threadIdx.x;
    size_t base = (size_t)row * DM;
    float v[4];
    float s = 0.f;
#pragma unroll
    for (int i = 0; i < 4; i++) {
        int c = tid + i * 128;
        float x = h[base + c] + delta[base + c];
        v[i] = x; s += x;
    }
    __shared__ float red[4];
    for (int o = 16; o; o >>= 1) s += __shfl_xor_sync(0xffffffffu, s, o);
    if ((tid & 31) == 0) red[tid >> 5] = s;
    __syncthreads();
    float mean = (red[0] + red[1] + red[2] + red[3]) * (1.f / 512.f);
    __syncthreads();
    float s2 = 0.f;
#pragma unroll
    for (int i = 0; i < 4; i++) { float d = v[i] - mean; s2 += d * d; }
    for (int o = 16; o; o >>= 1) s2 += __shfl_xor_sync(0xffffffffu, s2, o);
    if ((tid & 31) == 0) red[tid >> 5] = s2;
    __syncthreads();
    float var = (red[0] + red[1] + red[2] + red[3]) * (1.f / 512.f);
    float rstd = rsqrtf(var + 1e-5f);
#pragma unroll
    for (int i = 0; i < 4; i++) {
        int c = tid + i * 128;
        h[base + c] = (v[i] - mean) * rstd * g[c] + b[c];
    }
}

// Final projection: out[tok] = h[tok,:] . Wout.  Warp per token.
__global__ void out_kernel(const float* __restrict__ h, const float* __restrict__ W,
                           float* __restrict__ out) {
    int tok = blockIdx.x * 8 + (threadIdx.x >> 5);
    int lane = threadIdx.x & 31;
    const float* r = h + (size_t)tok * DM;
    float s = 0.f;
#pragma unroll
    for (int i = 0; i < 16; i++) s += r[lane + i * 32] * W[lane + i * 32];
    for (int o = 16; o; o >>= 1) s += __shfl_xor_sync(0xffffffffu, s, o);
    if (lane == 0) out[tok] = s;
}

// ---------------------------------------------------------------------------
// Weight prep (stacking)
// ---------------------------------------------------------------------------
__global__ void prep_wc_kernel(const float* __restrict__ W1s, const float* __restrict__ W1n,
                               const float* __restrict__ W2s, const float* __restrict__ W2n,
                               float* __restrict__ wc1, float* __restrict__ wc2) {
    int i = blockIdx.x * blockDim.x + threadIdx.x;
    if (i < 256 * 256) {
        int k = i >> 8, c = i & 255;
        wc1[i] = (k < 128) ? W1s[k * 256 + c] : W1n[(k - 128) * 256 + c];
    }
    if (i < 512 * 256) {
        int k = i >> 8, c = i & 255;
        wc2[i] = (k < 256) ? W2s[k * 256 + c] : W2n[(k - 256) * 256 + c];
    }
}

__global__ void prep_wqkv_kernel(const float* __restrict__ Wq, const float* __restrict__ Wk,
                                 const float* __restrict__ Wv,
                                 const float* __restrict__ bq, const float* __restrict__ bk,
                                 const float* __restrict__ bv,
                                 float* __restrict__ Wqkv, float* __restrict__ bqkv) {
    int i = blockIdx.x * blockDim.x + threadIdx.x;
    const int tot = 2 * 512 * 1536;
    if (i < tot) {
        int l = i / (512 * 1536);
        int rem = i % (512 * 1536);
        int r = rem / 1536, c = rem % 1536;
        float v;
        size_t wb = (size_t)l * 512 * 512 + (size_t)r * 512;
        if (c < 512)       v = Wq[wb + c];
        else if (c < 1024) v = Wk[wb + (c - 512)];
        else               v = Wv[wb + (c - 1024)];
        Wqkv[i] = v;
    }
    if (i < 2 * 1536) {
        int l = i / 1536, c = i % 1536;
        float v;
        if (c < 512)       v = bq[l * 512 + c];
        else if (c < 1024) v = bk[l * 512 + c - 512];
        else               v = bv[l * 512 + c - 1024];
        bqkv[i] = v;
    }
}

// ---------------------------------------------------------------------------
// Host driver
// ---------------------------------------------------------------------------
extern "C" void kernel_launch(void* const* d_in, const int* in_sizes, int n_in,
                              void* d_out, int out_size) {
    const float* x_i   = (const float*)d_in[0];
    const float* x_j   = (const float*)d_in[1];
    const int*   src_i = (const int*)d_in[2];
    const int*   dst_i = (const int*)d_in[3];
    const int*   src_j = (const int*)d_in[4];
    const int*   dst_j = (const int*)d_in[5];
    const int*   idx_i = (const int*)d_in[6];
    const int*   idx_j = (const int*)d_in[7];
    const float* W1s = (const float*)d_in[8];
    const float* W1n = (const float*)d_in[9];
    const float* b1  = (const float*)d_in[10];
    const float* W2s = (const float*)d_in[11];
    const float* W2n = (const float*)d_in[12];
    const float* b2  = (const float*)d_in[13];
    const float* Wq  = (const float*)d_in[14];
    const float* Wk  = (const float*)d_in[15];
    const float* Wv  = (const float*)d_in[16];
    const float* bq  = (const float*)d_in[17];
    const float* bk  = (const float*)d_in[18];
    const float* bv  = (const float*)d_in[19];
    const float* Wo  = (const float*)d_in[20];
    const float* bo  = (const float*)d_in[21];
    const float* Wf1 = (const float*)d_in[22];
    const float* bf1 = (const float*)d_in[23];
    const float* Wf2 = (const float*)d_in[24];
    const float* bf2 = (const float*)d_in[25];
    const float* g1  = (const float*)d_in[26];
    const float* bg1 = (const float*)d_in[27];
    const float* g2  = (const float*)d_in[28];
    const float* bg2 = (const float*)d_in[29];
    const float* Wout= (const float*)d_in[30];

    void* fp; cudaGetSymbolAddress(&fp, g_fblob);
    void* ip; cudaGetSymbolAddress(&ip, g_iblob);
    float* FB = (float*)fp;
    int*   IB = (int*)ip;

    float* bufA = FB + F_BUFA;
    float* h1   = FB + F_H1;
    float* bufB = FB + F_BUFB;
    float* h2   = FB + F_H2;
    float* wc1  = FB + F_WC1;
    float* wc2  = FB + F_WC2;
    float* wqkv = FB + F_WQKV;
    float* bqkv = FB + F_BQKV;
    float* hbuf = FB + F_H;
    float* qkv  = FB + F_QKV;
    float* tmp  = FB + F_TMP;
    float* ffb  = FB + F_FF;

    int* deg  = IB + I_DEG;
    int* cur  = IB + I_CUR;
    int* off  = IB + I_OFF;
    int* csrc = IB + I_CSR;

    float* att_out  = (float*)d_out;                       // [T, P, D]
    float* scal_out = att_out + (size_t)NTOK * DM;         // [T, P]

    // weight stacking (cheap, once per call)
    prep_wc_kernel<<<(512 * 256 + 255) / 256, 256>>>(W1s, W1n, W2s, W2n, wc1, wc2);
    prep_wqkv_kernel<<<(2 * 512 * 1536 + 255) / 256, 256>>>(Wq, Wk, Wv, bq, bk, bv, wqkv, bqkv);

    // ---------------- GraphSAGE for each (timestep, graph) ----------------
    for (int t = 0; t < TT; t++) {
        for (int g = 0; g < 2; g++) {
            const float* x   = (g == 0 ? x_i : x_j) + (size_t)t * NN * DIN;
            const int*   src = (g == 0 ? src_i : src_j) + (size_t)t * EE;
            const int*   dst = (g == 0 ? dst_i : dst_j) + (size_t)t * EE;
            const int*   idx = (g == 0 ? idx_i : idx_j) + (size_t)t * PP;

            zero_int_kernel<<<(40000 + 255) / 256, 256>>>(IB, 40000); // deg + cur
            hist_kernel<<<(EE + 255) / 256, 256>>>(dst, deg);
            scan_kernel<<<1, 1024>>>(deg, off);
            fill_kernel<<<(EE + 255) / 256, 256>>>(src, dst, off, cur, csrc);

            build_A_kernel<<<NN, 128>>>(x, 128, off, csrc, bufA);
            sgemm_kernel<1, 1><<<dim3(2, (NN + 127) / 128), 256>>>(bufA, wc1, b1, h1, NN, 256, 256);
            build_A_kernel<<<NN, 256>>>(h1, 256, off, csrc, bufB);
            sgemm_kernel<0, 1><<<dim3(2, (NN + 127) / 128), 256>>>(bufB, wc2, b2, h2, NN, 512, 256);
            rownorm_kernel<<<NN, 256>>>(h2);
            gather_kernel<<<PP, 256>>>(h2, idx, att_out, hbuf, t, g);
        }
    }

    // ---------------- Transformer ----------------
    for (int l = 0; l < NLAY; l++) {
        sgemm_kernel<0, 1><<<dim3(12, NTOK / 128), 256>>>(
            hbuf, wqkv + (size_t)l * 512 * 1536, bqkv + l * 1536, qkv, NTOK, 512, 1536);
        attn_kernel<<<PP * NHEAD, 128>>>(qkv, tmp);
        sgemm_kernel<0, 1><<<dim3(4, NTOK / 128), 256>>>(
            tmp, Wo + (size_t)l * 512 * 512, bo + l * 512, ffb /*as [NTOK,512]*/, NTOK, 512, 512);
        resid_ln_kernel<<<NTOK, 128>>>(hbuf, ffb, g1 + l * 512, bg1 + l * 512);
        sgemm_kernel<1, 1><<<dim3(16, NTOK / 128), 256>>>(
            hbuf, Wf1 + (size_t)l * 512 * 2048, bf1 + l * 2048, ffb, NTOK, 512, 2048);
        sgemm_kernel<0, 1><<<dim3(4, NTOK / 128), 256>>>(
            ffb, Wf2 + (size_t)l * 2048 * 512, bf2 + l * 512, tmp, NTOK, 2048, 512);
        resid_ln_kernel<<<NTOK, 128>>>(hbuf, tmp, g2 + l * 512, bg2 + l * 512);
    }

    out_kernel<<<NTOK / 8, 256>>>(hbuf, Wout, scal_out);
}

// round 2
// speedup vs baseline: 1.0043x; 1.0043x over previous
#include <cuda_runtime.h>

// ---------------------------------------------------------------------------
// Problem constants
// ---------------------------------------------------------------------------
#define TT     16
#define NN     20000
#define EE     320000
#define PP     4096
#define DIN    128
#define HH     256
#define NHEAD  8
#define NLAY   2
#define FF     2048
#define DM     512
#define HD     64
#define NTOK   (TT * PP)     // 65536

// ---------------------------------------------------------------------------
// Scratch blobs (no allocations allowed)
// ---------------------------------------------------------------------------
constexpr size_t F_BUFA = 0;                             // [20000, 256]  sage L1 input [x|agg]
constexpr size_t F_H1   = F_BUFA + 20000ull * 256;       // [20000, 256]  sage L1 out
constexpr size_t F_BUFB = F_H1   + 20000ull * 256;       // [20000, 512]  sage L2 input [h1|agg]
constexpr size_t F_H2   = F_BUFB + 20000ull * 512;       // [20000, 256]  sage L2 out
constexpr size_t F_WC1  = F_H2   + 20000ull * 256;       // [256, 256]    stacked W1
constexpr size_t F_WC2  = F_WC1  + 256ull * 256;         // [512, 256]    stacked W2
constexpr size_t F_WQKV = F_WC2  + 512ull * 256;         // [2, 512, 1536]
constexpr size_t F_BQKV = F_WQKV + 2ull * 512 * 1536;    // [2, 1536]
constexpr size_t F_H    = F_BQKV + 2ull * 1536;          // [65536, 512]  transformer hidden
constexpr size_t F_QKV  = F_H    + (size_t)NTOK * 512;   // [65536, 1536]
constexpr size_t F_TMP  = F_QKV  + (size_t)NTOK * 1536;  // [65536, 512]
constexpr size_t F_FF   = F_TMP  + (size_t)NTOK * 512;   // [65536, 2048]
constexpr size_t F_TOTAL= F_FF   + (size_t)NTOK * 2048;

__device__ float g_fblob[F_TOTAL];

constexpr size_t I_DEG = 0;
constexpr size_t I_CUR = 20000;
constexpr size_t I_OFF = 40000;          // N+1
constexpr size_t I_CSR = 60001;
constexpr size_t I_TOTAL = I_CSR + (size_t)EE;
__device__ int g_iblob[I_TOTAL];

// ---------------------------------------------------------------------------
// CSR construction
// ---------------------------------------------------------------------------
__global__ void zero_int_kernel(int* __restrict__ p, int n) {
    int i = blockIdx.x * blockDim.x + threadIdx.x;
    if (i < n) p[i] = 0;
}

__global__ void hist_kernel(const int* __restrict__ dst, int* __restrict__ deg) {
    int e = blockIdx.x * blockDim.x + threadIdx.x;
    if (e < EE) atomicAdd(&deg[dst[e]], 1);
}

__global__ void scan_kernel(const int* __restrict__ deg, int* __restrict__ off) {
    __shared__ int sd[1024];
    __shared__ int carry;
    int tid = threadIdx.x;
    if (tid == 0) { carry = 0; off[0] = 0; }
    __syncthreads();
    for (int base = 0; base < NN; base += 1024) {
        int i = base + tid;
        int v = (i < NN) ? deg[i] : 0;
        sd[tid] = v;
        __syncthreads();
        for (int o = 1; o < 1024; o <<= 1) {
            int t = (tid >= o) ? sd[tid - o] : 0;
            __syncthreads();
            sd[tid] += t;
            __syncthreads();
        }
        if (i < NN) off[i + 1] = carry + sd[tid];
        __syncthreads();
        if (tid == 0) carry += sd[1023];
        __syncthreads();
    }
}

__global__ void fill_kernel(const int* __restrict__ src, const int* __restrict__ dst,
                            const int* __restrict__ off, int* __restrict__ cur,
                            int* __restrict__ csrc) {
    int e = blockIdx.x * blockDim.x + threadIdx.x;
    if (e < EE) {
        int d = dst[e];
        int p = atomicAdd(&cur[d], 1);
        csrc[off[d] + p] = src[e];
    }
}

// ---------------------------------------------------------------------------
// Build A = [self | mean_agg] for a SAGE layer.  blockDim = F, grid = NN.
// ---------------------------------------------------------------------------
__global__ void build_A_kernel(const float* __restrict__ feat, int F,
                               const int* __restrict__ off, const int* __restrict__ csrc,
                               float* __restrict__ out) {
    int n = blockIdx.x;
    int f = threadIdx.x;
    float self = feat[(size_t)n * F + f];
    int s = off[n], e = off[n + 1];
    float acc = 0.f;
    int i = s;
    for (; i + 4 <= e; i += 4) {
        int a0 = csrc[i], a1 = csrc[i + 1], a2 = csrc[i + 2], a3 = csrc[i + 3];
        float v0 = feat[(size_t)a0 * F + f];
        float v1 = feat[(size_t)a1 * F + f];
        float v2 = feat[(size_t)a2 * F + f];
        float v3 = feat[(size_t)a3 * F + f];
        acc += v0 + v1 + v2 + v3;
    }
    for (; i < e; i++) acc += feat[(size_t)csrc[i] * F + f];
    int d = e - s; if (d < 1) d = 1;
    size_t ob = (size_t)n * (2 * F);
    out[ob + f]     = self;
    out[ob + F + f] = acc / (float)d;
}

// ---------------------------------------------------------------------------
// SGEMM: C[M,N] = A[M,K] @ B[K,N] (+bias) (+relu).  Row-major everywhere.
// 128x128 tile, BK=8, 256 threads, 8x8 per thread.
// Requires: K % 8 == 0, N % 128 == 0 (true for all call sites). M guarded.
// ---------------------------------------------------------------------------
template <int RELU, int BIAS>
__global__ void __launch_bounds__(256)
sgemm_kernel(const float* __restrict__ A, const float* __restrict__ B,
             const float* __restrict__ bias, float* __restrict__ C,
             int M, int K, int N) {
    __shared__ float As[8][128];
    __shared__ float Bs[8][128];
    int tid = threadIdx.x;
    int bm = blockIdx.y * 128;
    int bn = blockIdx.x * 128;
    int tx = tid & 15, ty = tid >> 4;
    int row0 = ty * 8, col0 = tx * 8;
    float acc[8][8];
#pragma unroll
    for (int i = 0; i < 8; i++)
#pragma unroll
        for (int j = 0; j < 8; j++) acc[i][j] = 0.f;

    int arow = tid >> 1;
    int acol = (tid & 1) * 4;
    int brow = tid >> 5;
    int bcol = (tid & 31) * 4;
    const float* Aptr = A + (size_t)(bm + arow) * K + acol;
    const float* Bptr = B + (size_t)brow * N + bn + bcol;
    bool arow_ok = (bm + arow) < M;

    for (int k0 = 0; k0 < K; k0 += 8) {
        float4 av = arow_ok ? *(const float4*)Aptr : make_float4(0.f, 0.f, 0.f, 0.f);
        float4 bv = *(const float4*)Bptr;
        As[acol + 0][arow] = av.x;
        As[acol + 1][arow] = av.y;
        As[acol + 2][arow] = av.z;
        As[acol + 3][arow] = av.w;
        *(float4*)&Bs[brow][bcol] = bv;
        __syncthreads();
#pragma unroll
        for (int kk = 0; kk < 8; kk++) {
            float a[8], b[8];
            *(float4*)&a[0] = *(const float4*)&As[kk][row0];
            *(float4*)&a[4] = *(const float4*)&As[kk][row0 + 4];
            *(float4*)&b[0] = *(const float4*)&Bs[kk][col0];
            *(float4*)&b[4] = *(const float4*)&Bs[kk][col0 + 4];
#pragma unroll
            for (int i = 0; i < 8; i++)
#pragma unroll
                for (int j = 0; j < 8; j++) acc[i][j] += a[i] * b[j];
        }
        __syncthreads();
        Aptr += 8;
        Bptr += (size_t)8 * N;
    }

#pragma unroll
    for (int i = 0; i < 8; i++) {
        int r = bm + row0 + i;
        if (r >= M) break;
        float* Crow = C + (size_t)r * N + bn + col0;
#pragma unroll
        for (int j = 0; j < 8; j++) {
            float v = acc[i][j];
            if (BIAS) v += bias[bn + col0 + j];
            if (RELU) v = fmaxf(v, 0.f);
            Crow[j] = v;
        }
    }
}

// ---------------------------------------------------------------------------
// Row L2-normalize, [NN, 256] in place.  grid = NN, block = 256.
// ---------------------------------------------------------------------------
__global__ void rownorm_kernel(float* __restrict__ h) {
    int n = blockIdx.x;
    int f = threadIdx.x;
    float v = h[(size_t)n * 256 + f];
    float s = v * v;
    __shared__ float red[8];
    for (int o = 16; o; o >>= 1) s += __shfl_xor_sync(0xffffffffu, s, o);
    if ((f & 31) == 0) red[f >> 5] = s;
    __syncthreads();
    float tot = red[0] + red[1] + red[2] + red[3] + red[4] + red[5] + red[6] + red[7];
    float norm = fmaxf(sqrtf(tot), 1e-12f);
    h[(size_t)n * 256 + f] = v / norm;
}

// Gather selected rows into att_in output AND transformer hidden init.
__global__ void gather_kernel(const float* __restrict__ h2, const int* __restrict__ idx,
                              float* __restrict__ att_out, float* __restrict__ hinit,
                              int t, int g) {
    int p = blockIdx.x;
    int f = threadIdx.x;      // 256
    int n = idx[p];
    float v = h2[(size_t)n * 256 + f];
    size_t o = ((size_t)(t * PP + p)) * DM + g * 256 + f;
    att_out[o] = v;
    hinit[o]   = v;
}

// ---------------------------------------------------------------------------
// Banded attention: window 4, T=16.  One block per (p, head), 128 threads.
// ---------------------------------------------------------------------------
__global__ void attn_kernel(const float* __restrict__ qkv, float* __restrict__ out) {
    int ph = blockIdx.x;
    int p = ph >> 3;
    int h = ph & 7;
    __shared__ float qs[16][64], ks[16][64], vs[16][64];
    int tid = threadIdx.x;
    for (int i = tid; i < 1024; i += 128) {
        int t = i >> 6, d = i & 63;
        const float* b = qkv + ((size_t)(t * PP + p)) * 1536 + h * 64 + d;
        qs[t][d] = b[0];
        ks[t][d] = b[512];
        vs[t][d] = b[1024];
    }
    __syncthreads();
    int warp = tid >> 5, lane = tid & 31;
    for (int t = warp; t < 16; t += 4) {
        int s0 = t - 3; if (s0 < 0) s0 = 0;
        int ns = t - s0 + 1;
        float sc[4];
        float mx = -1e30f;
        for (int si = 0; si < ns; si++) {
            int s = s0 + si;
            float d0 = qs[t][lane] * ks[s][lane] + qs[t][lane + 32] * ks[s][lane + 32];
            for (int o = 16; o; o >>= 1) d0 += __shfl_xor_sync(0xffffffffu, d0, o);
            d0 *= 0.125f;   // 1/sqrt(64)
            sc[si] = d0;
            mx = fmaxf(mx, d0);
        }
        float sum = 0.f;
        for (int si = 0; si < ns; si++) { sc[si] = expf(sc[si] - mx); sum += sc[si]; }
        float inv = 1.f / sum;
        float o0 = 0.f, o1 = 0.f;
        for (int si = 0; si < ns; si++) {
            int s = s0 + si;
            o0 += sc[si] * vs[s][lane];
            o1 += sc[si] * vs[s][lane + 32];
        }
        size_t ob = ((size_t)(t * PP + p)) * DM + h * 64;
        out[ob + lane]      = o0 * inv;
        out[ob + lane + 32] = o1 * inv;
    }
}

// ---------------------------------------------------------------------------
// h = LayerNorm(h + delta) * g + b.  grid = NTOK, block = 128, row = 512.
// ---------------------------------------------------------------------------
__global__ void resid_ln_kernel(float* __restrict__ h, const float* __restrict__ delta,
                                const float* __restrict__ g, const float* __restrict__ b) {
    int row = blockIdx.x;
    int tid = threadIdx.x;
    size_t base = (size_t)row * DM;
    float v[4];
    float s = 0.f;
#pragma unroll
    for (int i = 0; i < 4; i++) {
        int c = tid + i * 128;
        float x = h[base + c] + delta[base + c];
        v[i] = x; s += x;
    }
    __shared__ float red[4];
    for (int o = 16; o; o >>= 1) s += __shfl_xor_sync(0xffffffffu, s, o);
    if ((tid & 31) == 0) red[tid >> 5] = s;
    __syncthreads();
    float mean = (red[0] + red[1] + red[2] + red[3]) * (1.f / 512.f);
    __syncthreads();
    float s2 = 0.f;
#pragma unroll
    for (int i = 0; i < 4; i++) { float d = v[i] - mean; s2 += d * d; }
    for (int o = 16; o; o >>= 1) s2 += __shfl_xor_sync(0xffffffffu, s2, o);
    if ((tid & 31) == 0) red[tid >> 5] = s2;
    __syncthreads();
    float var = (red[0] + red[1] + red[2] + red[3]) * (1.f / 512.f);
    float rstd = rsqrtf(var + 1e-5f);
#pragma unroll
    for (int i = 0; i < 4; i++) {
        int c = tid + i * 128;
        h[base + c] = (v[i] - mean) * rstd * g[c] + b[c];
    }
}

// Final projection: out[tok] = h[tok,:] . Wout.  Warp per token.
__global__ void out_kernel(const float* __restrict__ h, const float* __restrict__ W,
                           float* __restrict__ out) {
    int tok = blockIdx.x * 8 + (threadIdx.x >> 5);
    int lane = threadIdx.x & 31;
    const float* r = h + (size_t)tok * DM;
    float s = 0.f;
#pragma unroll
    for (int i = 0; i < 16; i++) s += r[lane + i * 32] * W[lane + i * 32];
    for (int o = 16; o; o >>= 1) s += __shfl_xor_sync(0xffffffffu, s, o);
    if (lane == 0) out[tok] = s;
}

// ---------------------------------------------------------------------------
// Weight prep (stacking)
// ---------------------------------------------------------------------------
__global__ void prep_wc_kernel(const float* __restrict__ W1s, const float* __restrict__ W1n,
                               const float* __restrict__ W2s, const float* __restrict__ W2n,
                               float* __restrict__ wc1, float* __restrict__ wc2) {
    int i = blockIdx.x * blockDim.x + threadIdx.x;
    if (i < 256 * 256) {
        int k = i >> 8, c = i & 255;
        wc1[i] = (k < 128) ? W1s[k * 256 + c] : W1n[(k - 128) * 256 + c];
    }
    if (i < 512 * 256) {
        int k = i >> 8, c = i & 255;
        wc2[i] = (k < 256) ? W2s[k * 256 + c] : W2n[(k - 256) * 256 + c];
    }
}

__global__ void prep_wqkv_kernel(const float* __restrict__ Wq, const float* __restrict__ Wk,
                                 const float* __restrict__ Wv,
                                 const float* __restrict__ bq, const float* __restrict__ bk,
                                 const float* __restrict__ bv,
                                 float* __restrict__ Wqkv, float* __restrict__ bqkv) {
    int i = blockIdx.x * blockDim.x + threadIdx.x;
    const int tot = 2 * 512 * 1536;
    if (i < tot) {
        int l = i / (512 * 1536);
        int rem = i % (512 * 1536);
        int r = rem / 1536, c = rem % 1536;
        float v;
        size_t wb = (size_t)l * 512 * 512 + (size_t)r * 512;
        if (c < 512)       v = Wq[wb + c];
        else if (c < 1024) v = Wk[wb + (c - 512)];
        else               v = Wv[wb + (c - 1024)];
        Wqkv[i] = v;
    }
    if (i < 2 * 1536) {
        int l = i / 1536, c = i % 1536;
        float v;
        if (c < 512)       v = bq[l * 512 + c];
        else if (c < 1024) v = bk[l * 512 + c - 512];
        else               v = bv[l * 512 + c - 1024];
        bqkv[i] = v;
    }
}

// ---------------------------------------------------------------------------
// Host driver
// ---------------------------------------------------------------------------
extern "C" void kernel_launch(void* const* d_in, const int* in_sizes, int n_in,
                              void* d_out, int out_size) {
    const float* x_i   = (const float*)d_in[0];
    const float* x_j   = (const float*)d_in[1];
    const int*   src_i = (const int*)d_in[2];
    const int*   dst_i = (const int*)d_in[3];
    const int*   src_j = (const int*)d_in[4];
    const int*   dst_j = (const int*)d_in[5];
    const int*   idx_i = (const int*)d_in[6];
    const int*   idx_j = (const int*)d_in[7];
    const float* W1s = (const float*)d_in[8];
    const float* W1n = (const float*)d_in[9];
    const float* b1  = (const float*)d_in[10];
    const float* W2s = (const float*)d_in[11];
    const float* W2n = (const float*)d_in[12];
    const float* b2  = (const float*)d_in[13];
    const float* Wq  = (const float*)d_in[14];
    const float* Wk  = (const float*)d_in[15];
    const float* Wv  = (const float*)d_in[16];
    const float* bq  = (const float*)d_in[17];
    const float* bk  = (const float*)d_in[18];
    const float* bv  = (const float*)d_in[19];
    const float* Wo  = (const float*)d_in[20];
    const float* bo  = (const float*)d_in[21];
    const float* Wf1 = (const float*)d_in[22];
    const float* bf1 = (const float*)d_in[23];
    const float* Wf2 = (const float*)d_in[24];
    const float* bf2 = (const float*)d_in[25];
    const float* g1  = (const float*)d_in[26];
    const float* bg1 = (const float*)d_in[27];
    const float* g2  = (const float*)d_in[28];
    const float* bg2 = (const float*)d_in[29];
    const float* Wout= (const float*)d_in[30];

    void* fp; cudaGetSymbolAddress(&fp, g_fblob);
    void* ip; cudaGetSymbolAddress(&ip, g_iblob);
    float* FB = (float*)fp;
    int*   IB = (int*)ip;

    float* bufA = FB + F_BUFA;
    float* h1   = FB + F_H1;
    float* bufB = FB + F_BUFB;
    float* h2   = FB + F_H2;
    float* wc1  = FB + F_WC1;
    float* wc2  = FB + F_WC2;
    float* wqkv = FB + F_WQKV;
    float* bqkv = FB + F_BQKV;
    float* hbuf = FB + F_H;
    float* qkv  = FB + F_QKV;
    float* tmp  = FB + F_TMP;
    float* ffb  = FB + F_FF;

    int* deg  = IB + I_DEG;
    int* cur  = IB + I_CUR;
    int* off  = IB + I_OFF;
    int* csrc = IB + I_CSR;

    float* att_out  = (float*)d_out;                       // [T, P, D]
    float* scal_out = att_out + (size_t)NTOK * DM;         // [T, P]

    // weight stacking (cheap, once per call)
    prep_wc_kernel<<<(512 * 256 + 255) / 256, 256>>>(W1s, W1n, W2s, W2n, wc1, wc2);
    prep_wqkv_kernel<<<(2 * 512 * 1536 + 255) / 256, 256>>>(Wq, Wk, Wv, bq, bk, bv, wqkv, bqkv);

    // ---------------- GraphSAGE for each (timestep, graph) ----------------
    for (int t = 0; t < TT; t++) {
        for (int g = 0; g < 2; g++) {
            const float* x   = (g == 0 ? x_i : x_j) + (size_t)t * NN * DIN;
            const int*   src = (g == 0 ? src_i : src_j) + (size_t)t * EE;
            const int*   dst = (g == 0 ? dst_i : dst_j) + (size_t)t * EE;
            const int*   idx = (g == 0 ? idx_i : idx_j) + (size_t)t * PP;

            zero_int_kernel<<<(40000 + 255) / 256, 256>>>(IB, 40000); // deg + cur
            hist_kernel<<<(EE + 255) / 256, 256>>>(dst, deg);
            scan_kernel<<<1, 1024>>>(deg, off);
            fill_kernel<<<(EE + 255) / 256, 256>>>(src, dst, off, cur, csrc);

            build_A_kernel<<<NN, 128>>>(x, 128, off, csrc, bufA);
            sgemm_kernel<1, 1><<<dim3(2, (NN + 127) / 128), 256>>>(bufA, wc1, b1, h1, NN, 256, 256);
            build_A_kernel<<<NN, 256>>>(h1, 256, off, csrc, bufB);
            sgemm_kernel<0, 1><<<dim3(2, (NN + 127) / 128), 256>>>(bufB, wc2, b2, h2, NN, 512, 256);
            rownorm_kernel<<<NN, 256>>>(h2);
            gather_kernel<<<PP, 256>>>(h2, idx, att_out, hbuf, t, g);
        }
    }

    // ---------------- Transformer ----------------
    for (int l = 0; l < NLAY; l++) {
        sgemm_kernel<0, 1><<<dim3(12, NTOK / 128), 256>>>(
            hbuf, wqkv + (size_t)l * 512 * 1536, bqkv + l * 1536, qkv, NTOK, 512, 1536);
        attn_kernel<<<PP * NHEAD, 128>>>(qkv, tmp);
        sgemm_kernel<0, 1><<<dim3(4, NTOK / 128), 256>>>(
            tmp, Wo + (size_t)l * 512 * 512, bo + l * 512, ffb /*as [NTOK,512]*/, NTOK, 512, 512);
        resid_ln_kernel<<<NTOK, 128>>>(hbuf, ffb, g1 + l * 512, bg1 + l * 512);
        sgemm_kernel<1, 1><<<dim3(16, NTOK / 128), 256>>>(
            hbuf, Wf1 + (size_t)l * 512 * 2048, bf1 + l * 2048, ffb, NTOK, 512, 2048);
        sgemm_kernel<0, 1><<<dim3(4, NTOK / 128), 256>>>(
            ffb, Wf2 + (size_t)l * 2048 * 512, bf2 + l * 512, tmp, NTOK, 2048, 512);
        resid_ln_kernel<<<NTOK, 128>>>(hbuf, tmp, g2 + l * 512, bg2 + l * 512);
    }

    out_kernel<<<NTOK / 8, 256>>>(hbuf, Wout, scal_out);
}